// round 1
// baseline (speedup 1.0000x reference)
#include <cuda_runtime.h>

typedef unsigned long long ull;

#define NN 512
#define HD 128

// ---------------- scratch (no allocations allowed) ----------------
__device__ float g_A[NN * 256];
__device__ float g_B[NN * 256];
__device__ float g_S2[NN * 256];
__device__ float g_summ[NN * 128];
__device__ float g_gin[NN * 256];
__device__ float g_g1[NN * 256];
__device__ float g_g2[NN * 256];
__device__ float g_ig[NN * 128];
__device__ float g_gates[NN * 512];
__device__ float g_o1[NN * 256];

// ---------------- f32x2 packed helpers ----------------
__device__ __forceinline__ ull pack2(float lo, float hi) {
    ull r; asm("mov.b64 %0, {%1, %2};" : "=l"(r) : "f"(lo), "f"(hi)); return r;
}
__device__ __forceinline__ ull dup2(float x) {
    ull r; asm("mov.b64 %0, {%1, %1};" : "=l"(r) : "f"(x)); return r;
}
__device__ __forceinline__ void ffma2(ull& a, ull x, ull y) {
    asm("fma.rn.f32x2 %0, %1, %2, %0;" : "+l"(a) : "l"(x), "l"(y));
}
__device__ __forceinline__ void unpack2(ull v, float& lo, float& hi) {
    asm("mov.b64 {%0, %1}, %2;" : "=f"(lo), "=f"(hi) : "l"(v));
}

// ---------------- pairwise kernel ----------------
// One CTA per j. Computes S2[j, n] = sum_i relu( relu(A[i]+B[j]+bf1) @ Wf2^T + bf2 )[n]
// smem layout (floats):
//   sH1t [256][68]   (h1 transposed, k-major, pad 4 for aligned float4 + low-conflict writes)
//   sW   [16][256]   (Wf2 k-chunk)
//   sBb  [256], sb2 [256]
//   sRed [8][256]
#define PAIR_SMEM_FLOATS (256*68 + 16*256 + 256 + 256 + 8*256)

__global__ __launch_bounds__(256, 2) void pair_kernel(
    const float* __restrict__ A, const float* __restrict__ Bm,
    const float* __restrict__ bf1, const float* __restrict__ Wf2,
    const float* __restrict__ bf2, float* __restrict__ S2)
{
    extern __shared__ __align__(16) float sm[];
    float* sH1t = sm;                    // 256*68
    float* sW   = sm + 256 * 68;         // 16*256
    float* sBb  = sW + 16 * 256;         // 256
    float* sb2  = sBb + 256;             // 256
    float* sRed = sb2 + 256;             // 8*256

    const int j = blockIdx.x;
    const int t = threadIdx.x;
    sBb[t] = Bm[j * 256 + t] + bf1[t];
    sb2[t] = bf2[t];

    const int tx = t & 31;       // n = tx + 32*q
    const int ty = t >> 5;       // m0 = ty*8
    const int m0 = ty * 8;

    float s2acc[8] = {0.f, 0.f, 0.f, 0.f, 0.f, 0.f, 0.f, 0.f};
    __syncthreads();

    for (int ib = 0; ib < 8; ib++) {
        // ---- build h1^T tile: sH1t[k][m] = relu(A[i0+m, k] + B[j,k] + bf1[k]), k = t
        {
            const float bb = sBb[t];
            const float* Ap = A + (ib * 64) * 256 + t;
            float* dst = sH1t + t * 68;
#pragma unroll 8
            for (int r = 0; r < 64; r++) {
                dst[r] = fmaxf(Ap[r * 256] + bb, 0.f);
            }
        }

        ull acc[8][4];
#pragma unroll
        for (int q = 0; q < 8; q++)
#pragma unroll
            for (int mp = 0; mp < 4; mp++) acc[q][mp] = 0ULL;

        for (int k0 = 0; k0 < 256; k0 += 16) {
            // stage Wf2 chunk: sW[kk][n] = Wf2[n, k0+kk]; thread t owns row n=t
            float4 w0 = *(const float4*)(Wf2 + t * 256 + k0 + 0);
            float4 w1 = *(const float4*)(Wf2 + t * 256 + k0 + 4);
            float4 w2 = *(const float4*)(Wf2 + t * 256 + k0 + 8);
            float4 w3 = *(const float4*)(Wf2 + t * 256 + k0 + 12);
            __syncthreads();   // previous chunk fully consumed (also orders sH1t writes)
            sW[ 0 * 256 + t] = w0.x; sW[ 1 * 256 + t] = w0.y;
            sW[ 2 * 256 + t] = w0.z; sW[ 3 * 256 + t] = w0.w;
            sW[ 4 * 256 + t] = w1.x; sW[ 5 * 256 + t] = w1.y;
            sW[ 6 * 256 + t] = w1.z; sW[ 7 * 256 + t] = w1.w;
            sW[ 8 * 256 + t] = w2.x; sW[ 9 * 256 + t] = w2.y;
            sW[10 * 256 + t] = w2.z; sW[11 * 256 + t] = w2.w;
            sW[12 * 256 + t] = w3.x; sW[13 * 256 + t] = w3.y;
            sW[14 * 256 + t] = w3.z; sW[15 * 256 + t] = w3.w;
            __syncthreads();

#pragma unroll
            for (int kk = 0; kk < 16; kk++) {
                const float* hrow = sH1t + (k0 + kk) * 68 + m0;   // warp-broadcast
                float4 a0 = *(const float4*)(hrow);
                float4 a1 = *(const float4*)(hrow + 4);
                ull ap0 = pack2(a0.x, a0.y);
                ull ap1 = pack2(a0.z, a0.w);
                ull ap2 = pack2(a1.x, a1.y);
                ull ap3 = pack2(a1.z, a1.w);
                const float* wrow = sW + kk * 256 + tx;           // lane-stride-1 reads
#pragma unroll
                for (int q = 0; q < 8; q++) {
                    ull bq = dup2(wrow[q * 32]);
                    ffma2(acc[q][0], ap0, bq);
                    ffma2(acc[q][1], ap1, bq);
                    ffma2(acc[q][2], ap2, bq);
                    ffma2(acc[q][3], ap3, bq);
                }
            }
        }

        // ---- epilogue: relu(h2 + bf2), reduce this thread's 8 m-rows
#pragma unroll
        for (int q = 0; q < 8; q++) {
            const float b2 = sb2[tx + 32 * q];
            float s = 0.f;
#pragma unroll
            for (int mp = 0; mp < 4; mp++) {
                float lo, hi; unpack2(acc[q][mp], lo, hi);
                s += fmaxf(lo + b2, 0.f) + fmaxf(hi + b2, 0.f);
            }
            s2acc[q] += s;
        }
        __syncthreads();   // before next ib overwrites sH1t
    }

    // ---- cross-ty reduction (threads sharing n differ only in ty)
#pragma unroll
    for (int q = 0; q < 8; q++) sRed[ty * 256 + tx + 32 * q] = s2acc[q];
    __syncthreads();
    float v = 0.f;
#pragma unroll
    for (int r = 0; r < 8; r++) v += sRed[r * 256 + t];
    S2[j * 256 + t] = v;
}

// ---------------- generic small GEMM: C = act(X @ W^T + biasScale*bias [+ C]) ----------------
// grid.x = Nn/64, grid.y = M/64, 256 threads, 64x64 tile, 4x4 per thread
__global__ __launch_bounds__(256) void gemm_kernel(
    const float* __restrict__ X, int ldx,
    const float* __restrict__ W, int ldw,
    const float* __restrict__ bias, float biasScale,
    float* __restrict__ C, int ldc,
    int K, int act, int accum)
{
    __shared__ float sX[16][64];
    __shared__ float sWt[16][64];
    const int t = threadIdx.x;
    const int m0 = blockIdx.y * 64, n0 = blockIdx.x * 64;
    const int txn = t & 15, tym = t >> 4;
    const int lr = t >> 2;            // 0..63
    const int lc = (t & 3) * 4;       // 0,4,8,12

    float acc[4][4];
#pragma unroll
    for (int i = 0; i < 4; i++)
#pragma unroll
        for (int jj = 0; jj < 4; jj++) acc[i][jj] = 0.f;

    for (int k0 = 0; k0 < K; k0 += 16) {
        float4 xv = *(const float4*)(X + (m0 + lr) * ldx + k0 + lc);
        float4 wv = *(const float4*)(W + (n0 + lr) * ldw + k0 + lc);
        __syncthreads();
        sX[lc + 0][lr] = xv.x; sX[lc + 1][lr] = xv.y;
        sX[lc + 2][lr] = xv.z; sX[lc + 3][lr] = xv.w;
        sWt[lc + 0][lr] = wv.x; sWt[lc + 1][lr] = wv.y;
        sWt[lc + 2][lr] = wv.z; sWt[lc + 3][lr] = wv.w;
        __syncthreads();
#pragma unroll
        for (int kk = 0; kk < 16; kk++) {
            float a[4], b[4];
            *(float4*)a = *(const float4*)&sX[kk][tym * 4];
            *(float4*)b = *(const float4*)&sWt[kk][txn * 4];
#pragma unroll
            for (int i = 0; i < 4; i++)
#pragma unroll
                for (int jj = 0; jj < 4; jj++) acc[i][jj] = fmaf(a[i], b[jj], acc[i][jj]);
        }
    }

#pragma unroll
    for (int i = 0; i < 4; i++) {
        const int m = m0 + tym * 4 + i;
#pragma unroll
        for (int jj = 0; jj < 4; jj++) {
            const int n = n0 + txn * 4 + jj;
            float v = acc[i][jj];
            if (bias) v = fmaf(biasScale, bias[n], v);
            if (accum) v += C[m * ldc + n];
            if (act) v = fmaxf(v, 0.f);
            C[m * ldc + n] = v;
        }
    }
}

// ---------------- concat [x | summ] ----------------
__global__ void concat_kernel(const float* __restrict__ x,
                              const float* __restrict__ summ,
                              float* __restrict__ gin)
{
    int idx = blockIdx.x * blockDim.x + threadIdx.x;    // 512*256
    int n = idx >> 8, c = idx & 255;
    gin[idx] = (c < 128) ? x[n * 128 + c] : summ[n * 128 + (c - 128)];
}

// ---------------- LSTM elementwise ----------------
__global__ void lstm_kernel(const float* __restrict__ gates,
                            const float* __restrict__ c0,
                            float* __restrict__ out_h1,
                            float* __restrict__ out_h2,
                            float* __restrict__ out_c)
{
    int idx = blockIdx.x * blockDim.x + threadIdx.x;    // 512*128
    int n = idx >> 7, h = idx & 127;
    const float* gr = gates + n * 512;
    float ig = 1.f / (1.f + expf(-gr[h]));
    float fg = 1.f / (1.f + expf(-gr[128 + h]));
    float gg = tanhf(gr[256 + h]);
    float og = 1.f / (1.f + expf(-gr[384 + h]));
    float c = fg * c0[idx] + ig * gg;
    float hn = og * tanhf(c);
    out_h1[idx] = hn;
    out_h2[idx] = hn;
    out_c[idx]  = c;
}

// ---------------- launch ----------------
extern "C" void kernel_launch(void* const* d_in, const int* in_sizes, int n_in,
                              void* d_out, int out_size)
{
    const float* x    = (const float*)d_in[0];
    const float* hid  = (const float*)d_in[1];
    const float* h0   = (const float*)d_in[2];
    const float* c0   = (const float*)d_in[3];
    const float* Wf1  = (const float*)d_in[4];
    const float* bf1  = (const float*)d_in[5];
    const float* Wf2  = (const float*)d_in[6];
    const float* bf2  = (const float*)d_in[7];
    const float* Wf3  = (const float*)d_in[8];
    const float* bf3  = (const float*)d_in[9];
    const float* Wg1  = (const float*)d_in[10];
    const float* bg1  = (const float*)d_in[11];
    const float* Wg2  = (const float*)d_in[12];
    const float* bg2  = (const float*)d_in[13];
    const float* Wg3  = (const float*)d_in[14];
    const float* bg3  = (const float*)d_in[15];
    const float* W_ih = (const float*)d_in[16];
    const float* W_hh = (const float*)d_in[17];
    const float* b_ih = (const float*)d_in[18];
    const float* b_hh = (const float*)d_in[19];
    const float* Wo1  = (const float*)d_in[20];
    const float* bo1  = (const float*)d_in[21];
    const float* Wo2  = (const float*)d_in[22];
    const float* bo2  = (const float*)d_in[23];
    float* out = (float*)d_out;

    float *pA, *pB, *pS2, *psumm, *pgin, *pg1, *pg2, *pig, *pgates, *po1;
    cudaGetSymbolAddress((void**)&pA,     g_A);
    cudaGetSymbolAddress((void**)&pB,     g_B);
    cudaGetSymbolAddress((void**)&pS2,    g_S2);
    cudaGetSymbolAddress((void**)&psumm,  g_summ);
    cudaGetSymbolAddress((void**)&pgin,   g_gin);
    cudaGetSymbolAddress((void**)&pg1,    g_g1);
    cudaGetSymbolAddress((void**)&pg2,    g_g2);
    cudaGetSymbolAddress((void**)&pig,    g_ig);
    cudaGetSymbolAddress((void**)&pgates, g_gates);
    cudaGetSymbolAddress((void**)&po1,    g_o1);

    const int SMEM_PAIR = PAIR_SMEM_FLOATS * 4;
    cudaFuncSetAttribute(pair_kernel, cudaFuncAttributeMaxDynamicSharedMemorySize, SMEM_PAIR);

    dim3 blk(256);
    // A = hidden @ Wf1[:, :H]^T ; B = hidden @ Wf1[:, H:]^T
    gemm_kernel<<<dim3(4, 8), blk>>>(hid, 128, Wf1,       256, nullptr, 0.f, pA, 256, 128, 0, 0);
    gemm_kernel<<<dim3(4, 8), blk>>>(hid, 128, Wf1 + 128, 256, nullptr, 0.f, pB, 256, 128, 0, 0);

    // S2[j,n] = sum_i h2
    pair_kernel<<<512, 256, SMEM_PAIR>>>(pA, pB, bf1, Wf2, bf2, pS2);

    // sum_messages = S2 @ Wf3^T + 512*bf3
    gemm_kernel<<<dim3(2, 8), blk>>>(pS2, 256, Wf3, 256, bf3, 512.f, psumm, 128, 256, 0, 0);

    // g-MLP
    concat_kernel<<<512, 256>>>(x, psumm, pgin);
    gemm_kernel<<<dim3(4, 8), blk>>>(pgin, 256, Wg1, 256, bg1, 1.f, pg1, 256, 256, 1, 0);
    gemm_kernel<<<dim3(4, 8), blk>>>(pg1, 256, Wg2, 256, bg2, 1.f, pg2, 256, 256, 1, 0);
    gemm_kernel<<<dim3(2, 8), blk>>>(pg2, 256, Wg3, 256, bg3, 1.f, pig, 128, 256, 0, 0);

    // LSTM gates = input_g @ W_ih^T + b_ih + h0 @ W_hh^T + b_hh
    gemm_kernel<<<dim3(8, 8), blk>>>(pig, 128, W_ih, 128, b_ih, 1.f, pgates, 512, 128, 0, 0);
    gemm_kernel<<<dim3(8, 8), blk>>>(h0,  128, W_hh, 128, b_hh, 1.f, pgates, 512, 128, 0, 1);
    lstm_kernel<<<256, 256>>>(pgates, c0, out + 32768, out + 98304, out + 163840);

    // o-MLP
    gemm_kernel<<<dim3(4, 8), blk>>>(out + 32768, 128, Wo1, 128, bo1, 1.f, po1, 256, 128, 1, 0);
    gemm_kernel<<<dim3(1, 8), blk>>>(po1, 256, Wo2, 256, bo2, 1.f, out, 64, 256, 0, 0);
}

// round 4
// speedup vs baseline: 2.3644x; 2.3644x over previous
#include <cuda_runtime.h>
#include <cuda_bf16.h>
#include <cstdint>

#define NN 512

// ---------------- scratch (no allocations allowed) ----------------
__device__ float g_A[NN * 256];
__device__ float g_B[NN * 256];
__device__ float g_S2[NN * 256];
__device__ float g_summ[NN * 128];
__device__ float g_g1[NN * 256];
__device__ float g_g2[NN * 256];
__device__ float g_ig[NN * 128];
__device__ float g_gates[NN * 512];
__device__ float g_o1[NN * 256];
// Wf2 split into bf16 hi/lo, chunked layout [kc][n][64], 16B-typed for aligned uint4 LDG
__device__ uint4 g_Whi4[8192];
__device__ uint4 g_Wlo4[8192];

// ================= helpers =================
__device__ __forceinline__ uint32_t smem_u32(const void* p) {
    uint32_t a;
    asm("{ .reg .u64 t; cvta.to.shared.u64 t, %1; cvt.u32.u64 %0, t; }" : "=r"(a) : "l"(p));
    return a;
}

__device__ __forceinline__ void ldsm4(uint32_t (&r)[4], uint32_t addr) {
    asm volatile("ldmatrix.sync.aligned.m8n8.x4.shared.b16 {%0,%1,%2,%3}, [%4];"
        : "=r"(r[0]), "=r"(r[1]), "=r"(r[2]), "=r"(r[3]) : "r"(addr));
}

__device__ __forceinline__ void mma16816(float (&d)[4], const uint32_t (&a)[4],
                                         uint32_t b0, uint32_t b1) {
    asm volatile(
        "mma.sync.aligned.m16n8k16.row.col.f32.bf16.bf16.f32 "
        "{%0,%1,%2,%3}, {%4,%5,%6,%7}, {%8,%9}, {%0,%1,%2,%3};"
        : "+f"(d[0]), "+f"(d[1]), "+f"(d[2]), "+f"(d[3])
        : "r"(a[0]), "r"(a[1]), "r"(a[2]), "r"(a[3]), "r"(b0), "r"(b1));
}

// pack two floats to bf16x2 (round-to-nearest), f0 -> low half, f1 -> high half
__device__ __forceinline__ uint32_t pack_rn2(float f0, float f1) {
    uint32_t r; asm("cvt.rn.bf16x2.f32 %0, %1, %2;" : "=r"(r) : "f"(f1), "f"(f0));
    return r;
}

// ================= pair kernel smem layout (byte offsets from 128B-aligned base) =================
#define OFF_AHI 0u         // 16384
#define OFF_ALO 16384u     // 16384
#define OFF_WHI 32768u     // 32768
#define OFF_WLO 65536u     // 32768
#define OFF_BB  98304u     // 1024
#define OFF_B2  99328u     // 1024
#define OFF_RED 100352u    // 2048
#define PAIR_DYN_SMEM (102400u + 128u)

// ---------------- pairwise HMMA kernel ----------------
// One CTA per j. S2[j,n] = sum_i relu( relu(A[i]+B[j]+bf1) @ Wf2^T + bf2 )[n]
// 3-pass bf16 hi/lo split (hh + lh + hl), fp32 accumulate.
__global__ __launch_bounds__(256, 1) void pair_mma_kernel(
    const float* __restrict__ A, const float* __restrict__ Bm,
    const float* __restrict__ bf1, const float* __restrict__ bf2,
    float* __restrict__ S2)
{
    extern __shared__ __align__(16) char smraw[];
    const uint32_t raw = smem_u32(smraw);
    const uint32_t sb = (raw + 127u) & ~127u;
    char* smp = smraw + (sb - raw);

    const int j = blockIdx.x;
    const int t = threadIdx.x;
    const int lane = t & 31;
    const int w = t >> 5;
    const int wm = w >> 2;          // 0..1  (m-warp: 64 rows)
    const int wn = w & 3;           // 0..3  (n-warp: 64 cols)

    float* sBB = (float*)(smp + OFF_BB);
    float* sB2 = (float*)(smp + OFF_B2);
    float* sRED = (float*)(smp + OFF_RED);

    sBB[t] = Bm[j * 256 + t] + bf1[t];
    sB2[t] = bf2[t];

    // per-thread ldmatrix bases (XOR swizzle term: (lane&7)*16)
    const uint32_t lx = (uint32_t)(lane & 7) * 16u;
    const uint32_t rowOff = (uint32_t)(lane & 15) * 128u;
    const uint32_t segOff = (uint32_t)(lane >> 4) * 16u;
    const uint32_t aRowHi = sb + OFF_AHI + (uint32_t)(wm * 64) * 128u + rowOff;
    const uint32_t aRowLo = sb + OFF_ALO + (uint32_t)(wm * 64) * 128u + rowOff;
    const uint32_t wRowHi = sb + OFF_WHI + (uint32_t)(wn * 64) * 128u + rowOff;
    const uint32_t wRowLo = sb + OFF_WLO + (uint32_t)(wn * 64) * 128u + rowOff;

    // A staging coords: thread t handles row ar, k-half akh (32 k values)
    const int ar = t >> 1;
    const int akh = t & 1;

    float s[16];
#pragma unroll
    for (int q = 0; q < 16; q++) s[q] = 0.f;

    __syncthreads();

    for (int it = 0; it < 4; it++) {
        float acc[4][8][4];
#pragma unroll
        for (int mt = 0; mt < 4; mt++)
#pragma unroll
            for (int nt = 0; nt < 8; nt++)
#pragma unroll
                for (int e = 0; e < 4; e++) acc[mt][nt][e] = 0.f;

        for (int kc = 0; kc < 4; kc++) {
            __syncthreads();   // previous chunk's ldmatrix reads complete

            // ---- stage A chunk: h1 = relu(A + bb), split hi/lo bf16, swizzled
            {
                const float* ap = A + (it * 128 + ar) * 256 + kc * 64 + akh * 32;
                const float* bbp = sBB + kc * 64 + akh * 32;
                char* aHi = smp + OFF_AHI;
                char* aLo = smp + OFF_ALO;
                const uint32_t rbase = (uint32_t)(ar * 128 + akh * 64);
                const uint32_t rxor = (uint32_t)(ar & 7) * 16u;
#pragma unroll
                for (int g = 0; g < 4; g++) {
                    float4 v0 = *(const float4*)(ap + g * 8);
                    float4 v1 = *(const float4*)(ap + g * 8 + 4);
                    float4 b0 = *(const float4*)(bbp + g * 8);
                    float4 b1 = *(const float4*)(bbp + g * 8 + 4);
                    float f0 = fmaxf(v0.x + b0.x, 0.f), f1 = fmaxf(v0.y + b0.y, 0.f);
                    float f2 = fmaxf(v0.z + b0.z, 0.f), f3 = fmaxf(v0.w + b0.w, 0.f);
                    float f4 = fmaxf(v1.x + b1.x, 0.f), f5 = fmaxf(v1.y + b1.y, 0.f);
                    float f6 = fmaxf(v1.z + b1.z, 0.f), f7 = fmaxf(v1.w + b1.w, 0.f);
                    uint4 hp;
                    hp.x = pack_rn2(f0, f1); hp.y = pack_rn2(f2, f3);
                    hp.z = pack_rn2(f4, f5); hp.w = pack_rn2(f6, f7);
                    uint4 lp;
                    lp.x = pack_rn2(f0 - __uint_as_float(hp.x << 16),
                                    f1 - __uint_as_float(hp.x & 0xFFFF0000u));
                    lp.y = pack_rn2(f2 - __uint_as_float(hp.y << 16),
                                    f3 - __uint_as_float(hp.y & 0xFFFF0000u));
                    lp.z = pack_rn2(f4 - __uint_as_float(hp.z << 16),
                                    f5 - __uint_as_float(hp.z & 0xFFFF0000u));
                    lp.w = pack_rn2(f6 - __uint_as_float(hp.w << 16),
                                    f7 - __uint_as_float(hp.w & 0xFFFF0000u));
                    const uint32_t sw = (rbase + (uint32_t)g * 16u) ^ rxor;
                    *(uint4*)(aHi + sw) = hp;
                    *(uint4*)(aLo + sw) = lp;
                }
            }
            // ---- stage W chunk (prepped bf16 in gmem, chunk layout)
            // each 64-k row = 8 uint4 segments: n = li>>3, seg = li&7
            {
                const uint4* srcH = g_Whi4 + kc * 2048;
                const uint4* srcL = g_Wlo4 + kc * 2048;
                char* wHi = smp + OFF_WHI;
                char* wLo = smp + OFF_WLO;
#pragma unroll
                for (int r = 0; r < 8; r++) {
                    const int li = r * 256 + t;
                    const int n = li >> 3, seg = li & 7;
                    const uint32_t sw = ((uint32_t)(n * 128 + seg * 16)) ^ ((uint32_t)(n & 7) * 16u);
                    *(uint4*)(wHi + sw) = srcH[li];
                    *(uint4*)(wLo + sw) = srcL[li];
                }
            }
            __syncthreads();

            // ---- mma over 4 k-steps of 16
#pragma unroll
            for (int ks = 0; ks < 4; ks++) {
                const uint32_t kx = ((uint32_t)(ks * 32) + segOff) ^ lx;
                uint32_t aH[4][4], aL[4][4], wf[4][4];
#pragma unroll
                for (int mt = 0; mt < 4; mt++) ldsm4(aH[mt], aRowHi + mt * 2048 + kx);
#pragma unroll
                for (int np = 0; np < 4; np++) ldsm4(wf[np], wRowHi + np * 2048 + kx);
#pragma unroll
                for (int mt = 0; mt < 4; mt++)
#pragma unroll
                    for (int np = 0; np < 4; np++) {
                        mma16816(acc[mt][2 * np],     aH[mt], wf[np][0], wf[np][2]);
                        mma16816(acc[mt][2 * np + 1], aH[mt], wf[np][1], wf[np][3]);
                    }
#pragma unroll
                for (int mt = 0; mt < 4; mt++) ldsm4(aL[mt], aRowLo + mt * 2048 + kx);
#pragma unroll
                for (int mt = 0; mt < 4; mt++)
#pragma unroll
                    for (int np = 0; np < 4; np++) {
                        mma16816(acc[mt][2 * np],     aL[mt], wf[np][0], wf[np][2]);
                        mma16816(acc[mt][2 * np + 1], aL[mt], wf[np][1], wf[np][3]);
                    }
#pragma unroll
                for (int np = 0; np < 4; np++) ldsm4(wf[np], wRowLo + np * 2048 + kx);
#pragma unroll
                for (int mt = 0; mt < 4; mt++)
#pragma unroll
                    for (int np = 0; np < 4; np++) {
                        mma16816(acc[mt][2 * np],     aH[mt], wf[np][0], wf[np][2]);
                        mma16816(acc[mt][2 * np + 1], aH[mt], wf[np][1], wf[np][3]);
                    }
            }
        }

        // ---- fold: relu(h2 + bf2), sum over this tile's 128 i-rows
#pragma unroll
        for (int nt = 0; nt < 8; nt++) {
            const int col = wn * 64 + nt * 8 + (lane & 3) * 2;
            const float b20 = sB2[col], b21 = sB2[col + 1];
            float t0 = 0.f, t1 = 0.f;
#pragma unroll
            for (int mt = 0; mt < 4; mt++) {
                t0 += fmaxf(acc[mt][nt][0] + b20, 0.f) + fmaxf(acc[mt][nt][2] + b20, 0.f);
                t1 += fmaxf(acc[mt][nt][1] + b21, 0.f) + fmaxf(acc[mt][nt][3] + b21, 0.f);
            }
            s[nt * 2]     += t0;
            s[nt * 2 + 1] += t1;
        }
    }

    // ---- reduce over lanes with same (lane&3) (rows live in lane>>2)
#pragma unroll
    for (int q = 0; q < 16; q++) {
        s[q] += __shfl_xor_sync(0xFFFFFFFFu, s[q], 4);
        s[q] += __shfl_xor_sync(0xFFFFFFFFu, s[q], 8);
        s[q] += __shfl_xor_sync(0xFFFFFFFFu, s[q], 16);
    }
    __syncthreads();   // all mma/ldmatrix traffic done; safe to reuse RED region
    if (lane < 4) {
#pragma unroll
        for (int nt = 0; nt < 8; nt++) {
            const int col = wn * 64 + nt * 8 + lane * 2;
            sRED[wm * 256 + col]     = s[nt * 2];
            sRED[wm * 256 + col + 1] = s[nt * 2 + 1];
        }
    }
    __syncthreads();
    S2[j * 256 + t] = sRED[t] + sRED[256 + t];
}

// ---------------- Wf2 -> bf16 hi/lo chunked prep ----------------
__global__ void prep_w_kernel(const float* __restrict__ Wf2) {
    const int idx = blockIdx.x * 256 + threadIdx.x;   // 65536
    const int n = idx >> 8, k = idx & 255;
    const float v = Wf2[idx];
    const __nv_bfloat16 hb = __float2bfloat16(v);     // round-to-nearest
    const float lf = v - __bfloat162float(hb);
    const int o = (k >> 6) * 16384 + n * 64 + (k & 63);
    ((__nv_bfloat16*)g_Whi4)[o] = hb;
    ((__nv_bfloat16*)g_Wlo4)[o] = __float2bfloat16(lf);
}

// ---------------- small GEMM: C = act(X1@W1^T [+ X2@W2^T] + bScale*b1 [+ b2]) ----------------
// 32x32 tile, 256 threads, grid = (N/32, M/32)
__global__ __launch_bounds__(256) void gemm32(
    const float* __restrict__ X1, int ldx1,
    const float* __restrict__ W1, int ldw1, int K1,
    const float* __restrict__ X2, int ldx2,
    const float* __restrict__ W2, int ldw2, int K2,
    const float* __restrict__ b1, const float* __restrict__ b2p,
    float bScale, float* __restrict__ C, int ldc, int act)
{
    __shared__ float sX[32][34];
    __shared__ float sW[32][34];
    const int t = threadIdx.x;
    const int m0 = blockIdx.y * 32, n0 = blockIdx.x * 32;
    const int lm = t >> 3;
    const int lk = (t & 7) * 4;
    const int tm = (t >> 4) * 2;
    const int tn = (t & 15) * 2;

    const int nch1 = K1 >> 5;
    const int nch = nch1 + (X2 ? (K2 >> 5) : 0);

    float a00 = 0.f, a01 = 0.f, a10 = 0.f, a11 = 0.f;
    float4 xv = *(const float4*)(X1 + (m0 + lm) * ldx1 + lk);
    float4 wv = *(const float4*)(W1 + (n0 + lm) * ldw1 + lk);

    for (int c = 0; c < nch; c++) {
        __syncthreads();
        sX[lk + 0][lm] = xv.x; sX[lk + 1][lm] = xv.y;
        sX[lk + 2][lm] = xv.z; sX[lk + 3][lm] = xv.w;
        sW[lk + 0][lm] = wv.x; sW[lk + 1][lm] = wv.y;
        sW[lk + 2][lm] = wv.z; sW[lk + 3][lm] = wv.w;
        __syncthreads();
        const int cn = c + 1;
        if (cn < nch) {
            if (cn < nch1) {
                const int ko = cn * 32 + lk;
                xv = *(const float4*)(X1 + (m0 + lm) * ldx1 + ko);
                wv = *(const float4*)(W1 + (n0 + lm) * ldw1 + ko);
            } else {
                const int ko = (cn - nch1) * 32 + lk;
                xv = *(const float4*)(X2 + (m0 + lm) * ldx2 + ko);
                wv = *(const float4*)(W2 + (n0 + lm) * ldw2 + ko);
            }
        }
#pragma unroll
        for (int kk = 0; kk < 32; kk++) {
            float2 av = *(const float2*)&sX[kk][tm];
            float2 bv = *(const float2*)&sW[kk][tn];
            a00 = fmaf(av.x, bv.x, a00);
            a01 = fmaf(av.x, bv.y, a01);
            a10 = fmaf(av.y, bv.x, a10);
            a11 = fmaf(av.y, bv.y, a11);
        }
    }
    const int m = m0 + tm, n = n0 + tn;
    float bb0 = 0.f, bb1 = 0.f;
    if (b1)  { bb0 = bScale * b1[n]; bb1 = bScale * b1[n + 1]; }
    if (b2p) { bb0 += b2p[n];        bb1 += b2p[n + 1]; }
    float v00 = a00 + bb0, v01 = a01 + bb1, v10 = a10 + bb0, v11 = a11 + bb1;
    if (act) {
        v00 = fmaxf(v00, 0.f); v01 = fmaxf(v01, 0.f);
        v10 = fmaxf(v10, 0.f); v11 = fmaxf(v11, 0.f);
    }
    C[m * ldc + n] = v00;       C[m * ldc + n + 1] = v01;
    C[(m + 1) * ldc + n] = v10; C[(m + 1) * ldc + n + 1] = v11;
}

// ---------------- LSTM elementwise ----------------
__global__ void lstm_kernel(const float* __restrict__ gates,
                            const float* __restrict__ c0,
                            float* __restrict__ out_h1,
                            float* __restrict__ out_h2,
                            float* __restrict__ out_c)
{
    int idx = blockIdx.x * blockDim.x + threadIdx.x;    // 512*128
    int n = idx >> 7, h = idx & 127;
    const float* gr = gates + n * 512;
    float ig = 1.f / (1.f + expf(-gr[h]));
    float fg = 1.f / (1.f + expf(-gr[128 + h]));
    float gg = tanhf(gr[256 + h]);
    float og = 1.f / (1.f + expf(-gr[384 + h]));
    float c = fg * c0[idx] + ig * gg;
    float hn = og * tanhf(c);
    out_h1[idx] = hn;
    out_h2[idx] = hn;
    out_c[idx]  = c;
}

// ---------------- launch ----------------
extern "C" void kernel_launch(void* const* d_in, const int* in_sizes, int n_in,
                              void* d_out, int out_size)
{
    const float* x    = (const float*)d_in[0];
    const float* hid  = (const float*)d_in[1];
    const float* h0   = (const float*)d_in[2];
    const float* c0   = (const float*)d_in[3];
    const float* Wf1  = (const float*)d_in[4];
    const float* bf1  = (const float*)d_in[5];
    const float* Wf2  = (const float*)d_in[6];
    const float* bf2  = (const float*)d_in[7];
    const float* Wf3  = (const float*)d_in[8];
    const float* bf3  = (const float*)d_in[9];
    const float* Wg1  = (const float*)d_in[10];
    const float* bg1  = (const float*)d_in[11];
    const float* Wg2  = (const float*)d_in[12];
    const float* bg2  = (const float*)d_in[13];
    const float* Wg3  = (const float*)d_in[14];
    const float* bg3  = (const float*)d_in[15];
    const float* W_ih = (const float*)d_in[16];
    const float* W_hh = (const float*)d_in[17];
    const float* b_ih = (const float*)d_in[18];
    const float* b_hh = (const float*)d_in[19];
    const float* Wo1  = (const float*)d_in[20];
    const float* bo1  = (const float*)d_in[21];
    const float* Wo2  = (const float*)d_in[22];
    const float* bo2  = (const float*)d_in[23];
    float* out = (float*)d_out;

    float *pA, *pB, *pS2, *psumm, *pg1, *pg2, *pig, *pgates, *po1;
    cudaGetSymbolAddress((void**)&pA,     g_A);
    cudaGetSymbolAddress((void**)&pB,     g_B);
    cudaGetSymbolAddress((void**)&pS2,    g_S2);
    cudaGetSymbolAddress((void**)&psumm,  g_summ);
    cudaGetSymbolAddress((void**)&pg1,    g_g1);
    cudaGetSymbolAddress((void**)&pg2,    g_g2);
    cudaGetSymbolAddress((void**)&pig,    g_ig);
    cudaGetSymbolAddress((void**)&pgates, g_gates);
    cudaGetSymbolAddress((void**)&po1,    g_o1);

    cudaFuncSetAttribute(pair_mma_kernel, cudaFuncAttributeMaxDynamicSharedMemorySize, PAIR_DYN_SMEM);

    dim3 blk(256);

    // Wf2 bf16 hi/lo prep (chunked layout)
    prep_w_kernel<<<256, blk>>>(Wf2);

    // A = hidden @ Wf1[:, :128]^T ; B = hidden @ Wf1[:, 128:]^T
    gemm32<<<dim3(8, 16), blk>>>(hid, 128, Wf1,       256, 128, nullptr, 0, nullptr, 0, 0,
                                 nullptr, nullptr, 0.f, pA, 256, 0);
    gemm32<<<dim3(8, 16), blk>>>(hid, 128, Wf1 + 128, 256, 128, nullptr, 0, nullptr, 0, 0,
                                 nullptr, nullptr, 0.f, pB, 256, 0);

    // S2[j,n] = sum_i relu(relu(A_i + B_j + bf1) @ Wf2^T + bf2)
    pair_mma_kernel<<<512, blk, PAIR_DYN_SMEM>>>(pA, pB, bf1, bf2, pS2);

    // sum_messages = S2 @ Wf3^T + 512*bf3
    gemm32<<<dim3(4, 16), blk>>>(pS2, 256, Wf3, 256, 256, nullptr, 0, nullptr, 0, 0,
                                 bf3, nullptr, 512.f, psumm, 128, 0);

    // g1 = relu(x@Wg1a^T + summ@Wg1b^T + bg1)   (fused concat)
    gemm32<<<dim3(8, 16), blk>>>(x, 128, Wg1, 256, 128, psumm, 128, Wg1 + 128, 256, 128,
                                 bg1, nullptr, 1.f, pg1, 256, 1);
    // g2 = relu(g1@Wg2^T + bg2)
    gemm32<<<dim3(8, 16), blk>>>(pg1, 256, Wg2, 256, 256, nullptr, 0, nullptr, 0, 0,
                                 bg2, nullptr, 1.f, pg2, 256, 1);
    // input_g = g2@Wg3^T + bg3
    gemm32<<<dim3(4, 16), blk>>>(pg2, 256, Wg3, 256, 256, nullptr, 0, nullptr, 0, 0,
                                 bg3, nullptr, 1.f, pig, 128, 0);

    // gates = ig@W_ih^T + h0@W_hh^T + b_ih + b_hh   (fused)
    gemm32<<<dim3(16, 16), blk>>>(pig, 128, W_ih, 128, 128, h0, 128, W_hh, 128, 128,
                                  b_ih, b_hh, 1.f, pgates, 512, 0);
    lstm_kernel<<<256, blk>>>(pgates, c0, out + 32768, out + 98304, out + 163840);

    // o-MLP
    gemm32<<<dim3(8, 16), blk>>>(out + 32768, 128, Wo1, 128, 128, nullptr, 0, nullptr, 0, 0,
                                 bo1, nullptr, 1.f, po1, 256, 1);
    gemm32<<<dim3(2, 16), blk>>>(po1, 256, Wo2, 256, 256, nullptr, 0, nullptr, 0, 0,
                                 bo2, nullptr, 1.f, out, 64, 0);
}